// round 7
// baseline (speedup 1.0000x reference)
#include <cuda_runtime.h>

// Dice score: input (B=4, C=5, 128^3) fp32 logits, target (4, 128^3) int ids.
// pred = argmax over C; per-batch/class counts of pred/target/intersection
// (classes 1..4); dice = (2I+eps)/(P+T+eps); mean of 16 values -> out[0].
//
// Single kernel, single resident wave (512 blocks = 148 SMs x ~3.5 CTAs, all
// resident at once; work divides exactly). Per-thread byte-packed counters,
// 16-bit-field warp REDUX, shared atomics, returning global atomics (no
// __threadfence / L1 flush), last-block finalize. Last block re-zeroes
// scratch so "scratch == 0 at entry" holds for every graph replay.

#define NB 4
#define NC 5
#define NPOS (1 << 21)                   // 128^3
#define TPB 256
#define POS_PER_THREAD 64
#define POS_PER_BLOCK (TPB * POS_PER_THREAD)   // 16384, divides NPOS
#define NBLOCKS ((NB * NPOS) / POS_PER_BLOCK)  // 512 -> one resident wave
#define NQUAD (POS_PER_THREAD / 4)             // 16

// flat: [b][kind*4 + (c-1)], kind 0=pred,1=tgt,2=inter. Zero at entry.
__device__ int g_cnt[NB * 12];
__device__ unsigned g_ticket;

__global__ void __launch_bounds__(TPB, 4) k_count(const float* __restrict__ inp,
                                                  const void* __restrict__ tgt,
                                                  float* __restrict__ out) {
    // s_pack[kind*2 + h]: 16-bit fields, h=0 holds classes 1,3; h=1 holds 2,4
    __shared__ unsigned s_pack[6];
    __shared__ int s_is64;
    __shared__ int s_last;
    __shared__ int s_fin[NB * 12];
    volatile __shared__ int s_sink[12];
    const int tid  = threadIdx.x;
    const int lane = tid & 31;

    if (tid < 6) s_pack[tid] = 0;
    if (tid < 32) {
        // dtype probe: int32 read as int64 has a class id in the high word
        // whenever that word != 0; P(first 32 high words all zero) ~ (1/5)^32.
        long long v = ((const long long*)tgt)[tid];
        unsigned bad = __ballot_sync(0xffffffffu, v < 0 || v > (NC - 1));
        if (tid == 0) s_is64 = (bad == 0u);
    }
    __syncthreads();

    const long blockbase = (long)blockIdx.x * POS_PER_BLOCK;
    const int  b  = (int)(blockbase >> 21);
    const long n0 = (blockbase & (NPOS - 1)) + (long)tid * 4;
    const float* base = inp + (long)b * NC * NPOS + n0;
    const int is64 = s_is64;

    // byte-packed counters: byte (c-1) counts class c; max 64/byte here
    unsigned pp = 0u, tp = 0u, ip = 0u;

    #pragma unroll 4
    for (int j = 0; j < NQUAD; j++) {
        // ---- targets: 4 positions ----
        const long gq = (blockbase >> 2) + (long)j * TPB + tid;  // quad index
        int tv[4];
        if (is64) {
            longlong4 t4 = ((const longlong4*)tgt)[gq];
            tv[0] = (int)t4.x; tv[1] = (int)t4.y; tv[2] = (int)t4.z; tv[3] = (int)t4.w;
        } else {
            int4 t4 = ((const int4*)tgt)[gq];
            tv[0] = t4.x; tv[1] = t4.y; tv[2] = t4.z; tv[3] = t4.w;
        }

        // ---- logits: 5 classes x float4 ----
        float va[NC][4];
        #pragma unroll
        for (int c = 0; c < NC; c++) {
            float4 v = *(const float4*)(base + (long)c * NPOS + (long)j * (TPB * 4));
            va[c][0] = v.x; va[c][1] = v.y; va[c][2] = v.z; va[c][3] = v.w;
        }

        // ---- per position: max + predicated packed increments ----
        #pragma unroll
        for (int k = 0; k < 4; k++) {
            const float f1 = va[1][k], f2 = va[2][k],
                        f3 = va[3][k], f4 = va[4][k];
            const float m = fmaxf(fmaxf(fmaxf(va[0][k], f1), fmaxf(f2, f3)), f4);
            const int t = tv[k];

            if (f1 == m) pp += 1u;
            if (f2 == m) pp += 1u << 8;
            if (f3 == m) pp += 1u << 16;
            if (f4 == m) pp += 1u << 24;

            if (t) tp += 1u << ((t - 1) * 8);

            if (f1 == m && t == 1) ip += 1u;
            if (f2 == m && t == 2) ip += 1u << 8;
            if (f3 == m && t == 3) ip += 1u << 16;
            if (f4 == m && t == 4) ip += 1u << 24;
        }
    }

    // warp reduction: split bytes into 16-bit fields (warp sum <= 2048), REDUX
    {
        unsigned v[6];
        v[0] = pp & 0x00FF00FFu;  v[1] = (pp >> 8) & 0x00FF00FFu;
        v[2] = tp & 0x00FF00FFu;  v[3] = (tp >> 8) & 0x00FF00FFu;
        v[4] = ip & 0x00FF00FFu;  v[5] = (ip >> 8) & 0x00FF00FFu;
        #pragma unroll
        for (int i = 0; i < 6; i++)
            v[i] = __reduce_add_sync(0xffffffffu, v[i]);
        if (lane == 0) {
            #pragma unroll
            for (int i = 0; i < 6; i++) atomicAdd(&s_pack[i], v[i]);
        }
    }
    __syncthreads();

    // block -> global: returning atomics (completion = L2 updated), no fence
    if (tid < 12) {
        const int kind = tid >> 2;            // 0=pred,1=tgt,2=inter
        const int ci   = tid & 3;             // class-1
        const unsigned pk = s_pack[kind * 2 + (ci & 1)];
        const int cnt = (int)((pk >> (16 * (ci >> 1))) & 0xFFFFu);
        const int ret = atomicAdd(&g_cnt[b * 12 + tid], cnt);
        s_sink[tid] = ret;                    // consume: forces wait for ATOMG return
    }
    __syncthreads();

    // last-block election (all 12 adds of every arrived block are L2-complete)
    if (tid == 0) s_last = (atomicAdd(&g_ticket, 1u) == NBLOCKS - 1);
    __syncthreads();

    if (s_last) {
        if (tid < NB * 12) {
            s_fin[tid] = atomicAdd(&g_cnt[tid], 0);   // L2-coherent read
            g_cnt[tid] = 0;                           // zero-at-entry invariant
        }
        if (tid == 0) g_ticket = 0u;
        __syncthreads();
        if (tid == 0) {
            float acc = 0.0f;
            #pragma unroll
            for (int bb = 0; bb < NB; bb++) {
                #pragma unroll
                for (int ci = 0; ci < 4; ci++) {
                    const float I = (float)s_fin[bb * 12 + 8 + ci];
                    const float U = (float)(s_fin[bb * 12 + ci] +
                                            s_fin[bb * 12 + 4 + ci]);
                    acc += (2.0f * I + 1e-5f) / (U + 1e-5f);
                }
            }
            out[0] = acc * (1.0f / 16.0f);
        }
    }
}

extern "C" void kernel_launch(void* const* d_in, const int* in_sizes, int n_in,
                              void* d_out, int out_size) {
    const float* inp = (const float*)d_in[0];
    const void*  tgt = d_in[1];
    float* out = (float*)d_out;
    (void)in_sizes; (void)n_in; (void)out_size;

    k_count<<<NBLOCKS, TPB>>>(inp, tgt, out);
}

// round 8
// speedup vs baseline: 1.0300x; 1.0300x over previous
#include <cuda_runtime.h>

// Dice score: input (B=4, C=5, 128^3) fp32 logits, target (4, 128^3) int ids.
// pred = argmax over C; per-batch/class counts of pred/target/intersection
// (classes 1..4); dice = (2I+eps)/(P+T+eps); mean of 16 values -> out[0].
//
// Single kernel, grid = 4*148 blocks (every SM exactly 4 resident CTAs, no
// waves). Threads grid-stride over float4 "quads"; batch b = quad >> 19 is
// warp-uniform (all strides 32-aligned), so packed per-thread counters are
// REDUX-flushed per warp only when b changes. Fence-free returning-atomic
// block->global reduction + ticket last-block finalize; last block re-zeroes
// scratch so "scratch == 0 at entry" holds for every graph replay.

#define NB 4
#define NC 5
#define NPOS (1L << 21)                  // 128^3 positions per batch
#define BQ   (1L << 19)                  // quads per batch
#define NQ_TOT (NB * BQ)                 // 2^21 quads total
#define TPB 256
#define NBLOCKS (148 * 4)                // 592: one balanced resident wave
#define STRIDE ((long)NBLOCKS * TPB)     // 151552 quads per grid step

// flat: [b][kind*4 + (c-1)], kind 0=pred,1=tgt,2=inter. Zero at entry.
__device__ int g_cnt[NB * 12];
__device__ unsigned g_ticket;

__global__ void __launch_bounds__(TPB, 4) k_count(const float* __restrict__ inp,
                                                  const void* __restrict__ tgt,
                                                  float* __restrict__ out) {
    // s_pack[b][kind*2 + h]: 16-bit fields, h=0 -> classes 1,3; h=1 -> 2,4
    __shared__ unsigned s_pack[NB * 6];
    __shared__ int s_is64;
    __shared__ int s_last;
    __shared__ int s_fin[NB * 12];
    volatile __shared__ int s_sink[NB * 12];
    const int tid  = threadIdx.x;
    const int lane = tid & 31;

    if (tid < NB * 6) s_pack[tid] = 0;
    if (tid < 32) {
        // dtype probe: int32 read as int64 has a class id in the high word
        // whenever that word != 0; P(first 32 high words all zero) ~ (1/5)^32.
        long long v = ((const long long*)tgt)[tid];
        unsigned bad = __ballot_sync(0xffffffffu, v < 0 || v > (NC - 1));
        if (tid == 0) s_is64 = (bad == 0u);
    }
    __syncthreads();

    const int  is64 = s_is64;
    const long tid0 = (long)blockIdx.x * TPB + tid;

    // byte-packed counters for the CURRENT batch; byte (c-1) counts class c.
    // <= 4 quads * 4 pos = 16 increments per byte per batch. Warp-uniform b.
    unsigned pp = 0u, tp = 0u, ip = 0u;
    int bcur = 0;

#define FLUSH(BB, PP, TP, IP)                                              \
    do {                                                                   \
        unsigned v_[6];                                                    \
        v_[0] = (PP) & 0x00FF00FFu;  v_[1] = ((PP) >> 8) & 0x00FF00FFu;    \
        v_[2] = (TP) & 0x00FF00FFu;  v_[3] = ((TP) >> 8) & 0x00FF00FFu;    \
        v_[4] = (IP) & 0x00FF00FFu;  v_[5] = ((IP) >> 8) & 0x00FF00FFu;    \
        _Pragma("unroll")                                                  \
        for (int i_ = 0; i_ < 6; i_++)                                     \
            v_[i_] = __reduce_add_sync(0xffffffffu, v_[i_]);               \
        if (lane == 0) {                                                   \
            _Pragma("unroll")                                              \
            for (int i_ = 0; i_ < 6; i_++)                                 \
                atomicAdd(&s_pack[(BB) * 6 + i_], v_[i_]);                 \
        }                                                                  \
    } while (0)

    #pragma unroll 2
    for (long q = tid0; q < NQ_TOT; q += STRIDE) {
        const int b = (int)(q >> 19);               // warp-uniform
        if (b != bcur) {                            // taken <= 3 times
            FLUSH(bcur, pp, tp, ip);
            pp = tp = ip = 0u;
            bcur = b;
        }
        const long qi = q & (BQ - 1);               // quad within batch

        // ---- targets: 4 positions ----
        int tv[4];
        if (is64) {
            longlong4 t4 = ((const longlong4*)tgt)[q];
            tv[0] = (int)t4.x; tv[1] = (int)t4.y; tv[2] = (int)t4.z; tv[3] = (int)t4.w;
        } else {
            int4 t4 = ((const int4*)tgt)[q];
            tv[0] = t4.x; tv[1] = t4.y; tv[2] = t4.z; tv[3] = t4.w;
        }

        // ---- logits: 5 classes x float4 ----
        const float* base = inp + (long)b * (NC * NPOS) + (qi << 2);
        float va[NC][4];
        #pragma unroll
        for (int c = 0; c < NC; c++) {
            float4 v = *(const float4*)(base + (long)c * NPOS);
            va[c][0] = v.x; va[c][1] = v.y; va[c][2] = v.z; va[c][3] = v.w;
        }

        // ---- per position: max + predicated packed increments ----
        #pragma unroll
        for (int k = 0; k < 4; k++) {
            const float f1 = va[1][k], f2 = va[2][k],
                        f3 = va[3][k], f4 = va[4][k];
            const float m = fmaxf(fmaxf(fmaxf(va[0][k], f1), fmaxf(f2, f3)), f4);
            const int t = tv[k];

            if (f1 == m) pp += 1u;
            if (f2 == m) pp += 1u << 8;
            if (f3 == m) pp += 1u << 16;
            if (f4 == m) pp += 1u << 24;

            if (t) tp += 1u << ((t - 1) * 8);

            if (f1 == m && t == 1) ip += 1u;
            if (f2 == m && t == 2) ip += 1u << 8;
            if (f3 == m && t == 3) ip += 1u << 16;
            if (f4 == m && t == 4) ip += 1u << 24;
        }
    }
    FLUSH(bcur, pp, tp, ip);
    __syncthreads();

    // block -> global: returning atomics (completion = L2 updated), no fence
    if (tid < NB * 12) {
        const int bb   = tid / 12;
        const int idx  = tid - bb * 12;
        const int kind = idx >> 2;            // 0=pred,1=tgt,2=inter
        const int ci   = idx & 3;             // class-1
        const unsigned pk = s_pack[bb * 6 + kind * 2 + (ci & 1)];
        const int cnt = (int)((pk >> (16 * (ci >> 1))) & 0xFFFFu);
        const int ret = atomicAdd(&g_cnt[tid], cnt);
        s_sink[tid] = ret;                    // consume: waits for ATOMG return
    }
    __syncthreads();

    // last-block election (all 48 adds of every arrived block are L2-complete)
    if (tid == 0) s_last = (atomicAdd(&g_ticket, 1u) == NBLOCKS - 1);
    __syncthreads();

    if (s_last) {
        if (tid < NB * 12) {
            s_fin[tid] = atomicAdd(&g_cnt[tid], 0);   // L2-coherent read
            g_cnt[tid] = 0;                           // zero-at-entry invariant
        }
        if (tid == 0) g_ticket = 0u;
        __syncthreads();
        if (tid == 0) {
            float acc = 0.0f;
            #pragma unroll
            for (int bb = 0; bb < NB; bb++) {
                #pragma unroll
                for (int ci = 0; ci < 4; ci++) {
                    const float I = (float)s_fin[bb * 12 + 8 + ci];
                    const float U = (float)(s_fin[bb * 12 + ci] +
                                            s_fin[bb * 12 + 4 + ci]);
                    acc += (2.0f * I + 1e-5f) / (U + 1e-5f);
                }
            }
            out[0] = acc * (1.0f / 16.0f);
        }
    }
}

extern "C" void kernel_launch(void* const* d_in, const int* in_sizes, int n_in,
                              void* d_out, int out_size) {
    const float* inp = (const float*)d_in[0];
    const void*  tgt = d_in[1];
    float* out = (float*)d_out;
    (void)in_sizes; (void)n_in; (void)out_size;

    k_count<<<NBLOCKS, TPB>>>(inp, tgt, out);
}

// round 9
// speedup vs baseline: 1.0897x; 1.0580x over previous
#include <cuda_runtime.h>

// Dice score: input (B=4, C=5, 128^3) fp32 logits, target (4, 128^3) int ids.
// pred = argmax over C; per-batch/class counts of pred/target/intersection
// (classes 1..4); dice = (2I+eps)/(P+T+eps); mean of 16 values -> out[0].
//
// Single kernel, grid = 4*148 blocks (every SM 4 CTAs, one balanced wave).
// Threads grid-stride over float4 "quads" with 32-bit indices; batch
// b = quad >> 19 is warp-uniform, so packed per-thread counters are
// REDUX-flushed per warp only when b changes. Unroll-4 main loop for high
// per-warp MLP. Fence-free returning-atomic block->global reduction +
// ticket last-block finalize; last block re-zeroes scratch so
// "scratch == 0 at entry" holds for every graph replay.

#define NB 4
#define NC 5
#define BQ   (1u << 19)                  // quads per batch
#define NQ_TOT (NB * BQ)                 // 2^21 quads total
#define TPB 256
#define NBLOCKS (148 * 4)                // 592: one balanced resident wave
#define STRIDE ((unsigned)NBLOCKS * TPB) // 151552 quads per grid step

// flat: [b][kind*4 + (c-1)], kind 0=pred,1=tgt,2=inter. Zero at entry.
__device__ int g_cnt[NB * 12];
__device__ unsigned g_ticket;

__global__ void __launch_bounds__(TPB) k_count(const float* __restrict__ inp,
                                               const void* __restrict__ tgt,
                                               float* __restrict__ out) {
    // s_pack[b][kind*2 + h]: 16-bit fields, h=0 -> classes 1,3; h=1 -> 2,4
    __shared__ unsigned s_pack[NB * 6];
    __shared__ int s_is64;
    __shared__ int s_last;
    __shared__ int s_fin[NB * 12];
    volatile __shared__ int s_sink[NB * 12];
    const int tid  = threadIdx.x;
    const int lane = tid & 31;

    if (tid < NB * 6) s_pack[tid] = 0;
    if (tid < 32) {
        // dtype probe: int32 read as int64 has a class id in the high word
        // whenever that word != 0; P(first 32 high words all zero) ~ (1/5)^32.
        long long v = ((const long long*)tgt)[tid];
        unsigned bad = __ballot_sync(0xffffffffu, v < 0 || v > (NC - 1));
        if (tid == 0) s_is64 = (bad == 0u);
    }
    __syncthreads();

    const int is64 = s_is64;
    const unsigned tid0 = (unsigned)blockIdx.x * TPB + tid;
    const float4*    in4 = (const float4*)inp;
    const int4*      tg4 = (const int4*)tgt;
    const longlong4* tg8 = (const longlong4*)tgt;

    // byte-packed counters for the CURRENT batch; byte (c-1) counts class c.
    // <= 4 quads * 4 pos = 16 increments per byte per batch. Warp-uniform b.
    unsigned pp = 0u, tp = 0u, ip = 0u;
    int bcur = 0;

#define FLUSH(BB, PP, TP, IP)                                              \
    do {                                                                   \
        unsigned v_[6];                                                    \
        v_[0] = (PP) & 0x00FF00FFu;  v_[1] = ((PP) >> 8) & 0x00FF00FFu;    \
        v_[2] = (TP) & 0x00FF00FFu;  v_[3] = ((TP) >> 8) & 0x00FF00FFu;    \
        v_[4] = (IP) & 0x00FF00FFu;  v_[5] = ((IP) >> 8) & 0x00FF00FFu;    \
        _Pragma("unroll")                                                  \
        for (int i_ = 0; i_ < 6; i_++)                                     \
            v_[i_] = __reduce_add_sync(0xffffffffu, v_[i_]);               \
        if (lane == 0) {                                                   \
            _Pragma("unroll")                                              \
            for (int i_ = 0; i_ < 6; i_++)                                 \
                atomicAdd(&s_pack[(BB) * 6 + i_], v_[i_]);                 \
        }                                                                  \
    } while (0)

    #pragma unroll 4
    for (unsigned q = tid0; q < NQ_TOT; q += STRIDE) {
        const int b = (int)(q >> 19);               // warp-uniform
        if (b != bcur) {                            // taken <= 3 times
            FLUSH(bcur, pp, tp, ip);
            pp = tp = ip = 0u;
            bcur = b;
        }
        const unsigned qi = q & (BQ - 1u);          // quad within batch

        // ---- targets: 4 positions (one vec load) ----
        int tv[4];
        if (is64) {
            longlong4 t4 = tg8[q];
            tv[0] = (int)t4.x; tv[1] = (int)t4.y; tv[2] = (int)t4.z; tv[3] = (int)t4.w;
        } else {
            int4 t4 = tg4[q];
            tv[0] = t4.x; tv[1] = t4.y; tv[2] = t4.z; tv[3] = t4.w;
        }

        // ---- logits: 5 classes x float4 (32-bit indices) ----
        const unsigned fbase = (unsigned)b * (NC * BQ) + qi;
        float va[NC][4];
        #pragma unroll
        for (int c = 0; c < NC; c++) {
            float4 v = in4[fbase + (unsigned)c * BQ];
            va[c][0] = v.x; va[c][1] = v.y; va[c][2] = v.z; va[c][3] = v.w;
        }

        // ---- per position: max + predicated packed increments ----
        #pragma unroll
        for (int k = 0; k < 4; k++) {
            const float f1 = va[1][k], f2 = va[2][k],
                        f3 = va[3][k], f4 = va[4][k];
            const float m = fmaxf(fmaxf(fmaxf(va[0][k], f1), fmaxf(f2, f3)), f4);
            const int t = tv[k];

            if (f1 == m) pp += 1u;
            if (f2 == m) pp += 1u << 8;
            if (f3 == m) pp += 1u << 16;
            if (f4 == m) pp += 1u << 24;

            if (t) tp += 1u << ((t - 1) * 8);

            if (f1 == m && t == 1) ip += 1u;
            if (f2 == m && t == 2) ip += 1u << 8;
            if (f3 == m && t == 3) ip += 1u << 16;
            if (f4 == m && t == 4) ip += 1u << 24;
        }
    }
    FLUSH(bcur, pp, tp, ip);
    __syncthreads();

    // block -> global: returning atomics (completion = L2 updated), no fence
    if (tid < NB * 12) {
        const int bb   = tid / 12;
        const int idx  = tid - bb * 12;
        const int kind = idx >> 2;            // 0=pred,1=tgt,2=inter
        const int ci   = idx & 3;             // class-1
        const unsigned pk = s_pack[bb * 6 + kind * 2 + (ci & 1)];
        const int cnt = (int)((pk >> (16 * (ci >> 1))) & 0xFFFFu);
        const int ret = atomicAdd(&g_cnt[tid], cnt);
        s_sink[tid] = ret;                    // consume: waits for ATOMG return
    }
    __syncthreads();

    // last-block election (all 48 adds of every arrived block are L2-complete)
    if (tid == 0) s_last = (atomicAdd(&g_ticket, 1u) == NBLOCKS - 1);
    __syncthreads();

    if (s_last) {
        if (tid < NB * 12) {
            s_fin[tid] = atomicAdd(&g_cnt[tid], 0);   // L2-coherent read
            g_cnt[tid] = 0;                           // zero-at-entry invariant
        }
        if (tid == 0) g_ticket = 0u;
        __syncthreads();
        if (tid == 0) {
            float acc = 0.0f;
            #pragma unroll
            for (int bb = 0; bb < NB; bb++) {
                #pragma unroll
                for (int ci = 0; ci < 4; ci++) {
                    const float I = (float)s_fin[bb * 12 + 8 + ci];
                    const float U = (float)(s_fin[bb * 12 + ci] +
                                            s_fin[bb * 12 + 4 + ci]);
                    acc += (2.0f * I + 1e-5f) / (U + 1e-5f);
                }
            }
            out[0] = acc * (1.0f / 16.0f);
        }
    }
}

extern "C" void kernel_launch(void* const* d_in, const int* in_sizes, int n_in,
                              void* d_out, int out_size) {
    const float* inp = (const float*)d_in[0];
    const void*  tgt = d_in[1];
    float* out = (float*)d_out;
    (void)in_sizes; (void)n_in; (void)out_size;

    k_count<<<NBLOCKS, TPB>>>(inp, tgt, out);
}